// round 1
// baseline (speedup 1.0000x reference)
#include <cuda_runtime.h>
#include <cstdint>

#define NSPEC 1024
#define NR1   2048
#define NR2   8192
#define NB    32            // batches per CTA (lane dimension)
#define WARPS 16            // warps per CTA
#define PROD_PER_WARP (NSPEC / WARPS)   // 64
#define YPITCH 33           // +1 padding for conflict-free transposed access

// ---------------- device scratch (no allocations allowed) ----------------
__device__ int  g_off1[NSPEC + 1];
__device__ int  g_off2[NSPEC + 1];
__device__ int  g_cur1[NSPEC];
__device__ int  g_cur2[NSPEC];
__device__ int2 g_e1[NR1];   // .x = reactant_idx | (product_idx << 16), .y = bitcast(k)
__device__ int4 g_e2[NR2];   // .x = ir0, .y = ir1, .z = bitcast(k), .w = product_idx

// ---------------- block-wide inclusive scan (1024 threads) ----------------
__device__ __forceinline__ int block_scan_inclusive(int v, int* tmp) {
    const int lane = threadIdx.x & 31;
    const int wid  = threadIdx.x >> 5;
#pragma unroll
    for (int d = 1; d < 32; d <<= 1) {
        int n = __shfl_up_sync(0xFFFFFFFFu, v, d);
        if (lane >= d) v += n;
    }
    if (lane == 31) tmp[wid] = v;
    __syncthreads();
    if (wid == 0) {
        int w = tmp[lane];
#pragma unroll
        for (int d = 1; d < 32; d <<= 1) {
            int n = __shfl_up_sync(0xFFFFFFFFu, w, d);
            if (lane >= d) w += n;
        }
        tmp[lane] = w;
    }
    __syncthreads();
    if (wid > 0) v += tmp[wid - 1];
    return v;
}

// ---------------- setup 1: histogram + scan -> CSR offsets ----------------
__global__ void setup_scan_kernel(const int* __restrict__ i1p,
                                  const int* __restrict__ i2p) {
    __shared__ int c1[NSPEC];
    __shared__ int c2[NSPEC];
    __shared__ int tmp[32];
    const int t = threadIdx.x;
    c1[t] = 0; c2[t] = 0;
    __syncthreads();
    for (int i = t; i < NR1; i += 1024) atomicAdd(&c1[i1p[i]], 1);
    for (int i = t; i < NR2; i += 1024) atomicAdd(&c2[i2p[i]], 1);
    __syncthreads();
    const int v1 = c1[t];
    const int v2 = c2[t];
    int s1 = block_scan_inclusive(v1, tmp);
    __syncthreads();
    int s2 = block_scan_inclusive(v2, tmp);
    const int e1 = s1 - v1;   // exclusive
    const int e2 = s2 - v2;
    g_off1[t] = e1;  g_cur1[t] = e1;
    g_off2[t] = e2;  g_cur2[t] = e2;
    if (t == NSPEC - 1) { g_off1[NSPEC] = s1; g_off2[NSPEC] = s2; }
}

// ---------------- setup 2: scatter reactions into CSR entry arrays --------
__global__ void setup_scatter_kernel(const int*   __restrict__ i1r,
                                     const int*   __restrict__ i1p,
                                     const float* __restrict__ k1,
                                     const int*   __restrict__ i2r,
                                     const int*   __restrict__ i2p,
                                     const float* __restrict__ k2) {
    const int tid    = blockIdx.x * blockDim.x + threadIdx.x;
    const int stride = gridDim.x * blockDim.x;
    for (int r = tid; r < NR1; r += stride) {
        const int p   = i1p[r];
        const int pos = atomicAdd(&g_cur1[p], 1);
        g_e1[pos] = make_int2((i1r[r] & 0xFFFF) | (p << 16), __float_as_int(k1[r]));
    }
    for (int r = tid; r < NR2; r += stride) {
        const int p   = i2p[r];
        const int pos = atomicAdd(&g_cur2[p], 1);
        g_e2[pos] = make_int4(i2r[2 * r], i2r[2 * r + 1], __float_as_int(k2[r]), p);
    }
}

// ---------------- main kernel ---------------------------------------------
// One CTA = 32 batches. smem:
//   y_s   [NSPEC][YPITCH]  transposed y rows (gathers conflict-free, lane=batch)
//   t_s   [NB]             per-batch t
//   otile [WARPS][32][YPITCH] per-warp output transpose staging
#define SMEM_FLOATS (NSPEC * YPITCH + NB + WARPS * 32 * YPITCH)
#define SMEM_BYTES  (SMEM_FLOATS * 4)

extern "C" __global__ void __launch_bounds__(WARPS * 32, 1)
reaction_main_kernel(const float* __restrict__ t_in,
                     const float* __restrict__ y_in,
                     float* __restrict__ y_out) {
    extern __shared__ float smem[];
    float* y_s   = smem;                         // NSPEC * YPITCH
    float* t_s   = y_s + NSPEC * YPITCH;         // NB
    float* otile0 = t_s + NB;                    // WARPS * 32 * YPITCH

    const int tid  = threadIdx.x;
    const int lane = tid & 31;
    const int warp = tid >> 5;
    const int b0   = blockIdx.x * NB;

    if (tid < NB) t_s[tid] = t_in[b0 + tid];

    // load 32 y rows, transposed into smem (coalesced LDG, conflict-free STS)
    for (int i = tid; i < NB * NSPEC; i += WARPS * 32) {
        const int b = i >> 10;          // NSPEC == 1024
        const int s = i & (NSPEC - 1);
        y_s[s * YPITCH + b] = y_in[(size_t)(b0 + b) * NSPEC + s];
    }
    __syncthreads();

    float* otile = otile0 + warp * (32 * YPITCH);

    // each warp owns PROD_PER_WARP consecutive products, in chunks of 32
    for (int pc = warp * PROD_PER_WARP; pc < (warp + 1) * PROD_PER_WARP; pc += 32) {
#pragma unroll
        for (int pp = 0; pp < 32; ++pp) otile[pp * YPITCH + lane] = 0.0f;
        __syncwarp();

        // ---- first-order stream (contiguous CSR range for this chunk) ----
        {
            int j        = g_off1[pc];
            const int j1 = g_off1[pc + 32];
            float acc = 0.0f;
            int curp = -1;
#pragma unroll 4
            for (; j < j1; ++j) {
                const int2 e = g_e1[j];
                const int p  = e.x >> 16;
                const int ir = e.x & 0xFFFF;
                if (p != curp) {
                    if (curp >= 0) otile[(curp - pc) * YPITCH + lane] += acc;
                    acc  = 0.0f;
                    curp = p;
                }
                acc = fmaf(__int_as_float(e.y), y_s[ir * YPITCH + lane], acc);
            }
            if (curp >= 0) otile[(curp - pc) * YPITCH + lane] += acc;
        }

        // ---- second-order stream ----
        {
            int j        = g_off2[pc];
            const int j1 = g_off2[pc + 32];
            float acc = 0.0f;
            int curp = -1;
#pragma unroll 4
            for (; j < j1; ++j) {
                const int4 e = g_e2[j];
                if (e.w != curp) {
                    if (curp >= 0) otile[(curp - pc) * YPITCH + lane] += acc;
                    acc  = 0.0f;
                    curp = e.w;
                }
                const float yy = y_s[e.x * YPITCH + lane] * y_s[e.y * YPITCH + lane];
                acc = fmaf(__int_as_float(e.z), yy, acc);
            }
            if (curp >= 0) otile[(curp - pc) * YPITCH + lane] += acc;
        }
        __syncwarp();

        // ---- transpose store: coalesced 128B STG per row ----
#pragma unroll
        for (int row = 0; row < 32; ++row) {
            y_out[(size_t)(b0 + row) * NSPEC + pc + lane] =
                otile[lane * YPITCH + row] * t_s[row];
        }
        __syncwarp();
    }
}

// ---------------- launch ---------------------------------------------------
extern "C" void kernel_launch(void* const* d_in, const int* in_sizes, int n_in,
                              void* d_out, int out_size) {
    const float* t_in = (const float*)d_in[0];
    const float* y_in = (const float*)d_in[1];
    const float* k1   = (const float*)d_in[2];
    const float* k2   = (const float*)d_in[3];
    const int*   i1r  = (const int*)d_in[4];
    const int*   i1p  = (const int*)d_in[5];
    const int*   i2r  = (const int*)d_in[6];
    const int*   i2p  = (const int*)d_in[7];
    float* y_out = (float*)d_out;

    const int B = in_sizes[0];

    setup_scan_kernel<<<1, 1024>>>(i1p, i2p);
    setup_scatter_kernel<<<32, 256>>>(i1r, i1p, k1, i2r, i2p, k2);

    cudaFuncSetAttribute(reaction_main_kernel,
                         cudaFuncAttributeMaxDynamicSharedMemorySize, SMEM_BYTES);
    reaction_main_kernel<<<B / NB, WARPS * 32, SMEM_BYTES>>>(t_in, y_in, y_out);
}

// round 2
// speedup vs baseline: 1.3710x; 1.3710x over previous
#include <cuda_runtime.h>
#include <cstdint>

#define NSPEC 1024
#define NR1   2048
#define NR2   8192
#define NRTOT (NR1 + NR2)
#define NB    32                 // batches per CTA (lane dimension)
#define WARPS 16                 // warps per CTA
#define THREADS (WARPS * 32)
#define PROD_PER_WARP (NSPEC / WARPS)   // 64
#define YP    33                 // +1 pad: conflict-free transposed access
#define ONES_ROW NSPEC           // y_s row holding 1.0f (first-order trick)

// ---------------- device scratch (no allocations allowed) ----------------
__device__ int  g_off[NSPEC + 1];
__device__ int4 g_e[NRTOT];      // .x=ir0  .y=ir1(or ONES_ROW)  .z=bits(k)  .w=product
__device__ int  g_ready;         // setup-done flag (reset at kernel end)
__device__ int  g_done;          // CTA completion counter (reset at kernel end)

// ---------------- smem layout (floats) -------------------------------------
// [0 .. 2048)                       : entry staging, 16 warps x 32 int4 (16B aligned)
// [2048 .. 2048+33825)              : y_s (NSPEC+1 rows x YP)
// [.. +32)                          : t_s
// [.. +16896)                       : otile, 16 warps x 32 x YP  (also aliased as setup scratch)
#define SBUF_FLOATS   (WARPS * 32 * 4)
#define YS_FLOATS     ((NSPEC + 1) * YP)
#define OTILE_FLOATS  (WARPS * 32 * YP)
#define SMEM_FLOATS   (SBUF_FLOATS + YS_FLOATS + NB + OTILE_FLOATS)
#define SMEM_BYTES    (SMEM_FLOATS * 4)

extern "C" __global__ void __launch_bounds__(THREADS, 1)
reaction_fused_kernel(const float* __restrict__ t_in,
                      const float* __restrict__ y_in,
                      const float* __restrict__ k1,
                      const float* __restrict__ k2,
                      const int*   __restrict__ i1r,
                      const int*   __restrict__ i1p,
                      const int*   __restrict__ i2r,
                      const int*   __restrict__ i2p,
                      float* __restrict__ y_out,
                      int grid_size) {
    extern __shared__ float smem[];
    int4*  sbuf_all = (int4*)smem;                         // WARPS*32 int4
    float* y_s      = smem + SBUF_FLOATS;                  // (NSPEC+1)*YP
    float* t_s      = y_s + YS_FLOATS;                     // NB
    float* otile0   = t_s + NB;                            // WARPS*32*YP

    const int tid  = threadIdx.x;
    const int lane = tid & 31;
    const int warp = tid >> 5;
    const int b0   = blockIdx.x * NB;

    // ================= CTA 0: build CSR (others overlap y-tile load) =======
    if (blockIdx.x == 0) {
        int* s_cnt  = (int*)otile0;          // 1024 (aliased into otile, used pre-mainloop)
        int* s_cur  = s_cnt + NSPEC;         // 1024
        int* s_wsum = s_cur + NSPEC;         // 16

        // histogram of product indices
        s_cnt[2 * tid]     = 0;
        s_cnt[2 * tid + 1] = 0;
        __syncthreads();
        for (int i = tid; i < NR1; i += THREADS) atomicAdd(&s_cnt[i1p[i]], 1);
        for (int i = tid; i < NR2; i += THREADS) atomicAdd(&s_cnt[i2p[i]], 1);
        __syncthreads();

        // exclusive scan over 1024 bins (each thread owns 2 bins)
        const int a = s_cnt[2 * tid];
        const int b = s_cnt[2 * tid + 1];
        int incl = a + b;
#pragma unroll
        for (int d = 1; d < 32; d <<= 1) {
            int n = __shfl_up_sync(0xFFFFFFFFu, incl, d);
            if (lane >= d) incl += n;
        }
        if (lane == 31) s_wsum[warp] = incl;
        __syncthreads();
        if (warp == 0) {
            int w = (lane < WARPS) ? s_wsum[lane] : 0;
#pragma unroll
            for (int d = 1; d < 32; d <<= 1) {
                int n = __shfl_up_sync(0xFFFFFFFFu, w, d);
                if (lane >= d) w += n;
            }
            if (lane < WARPS) s_wsum[lane] = w;
        }
        __syncthreads();
        if (warp > 0) incl += s_wsum[warp - 1];
        const int e0 = incl - a - b;                 // exclusive offset, bin 2*tid
        g_off[2 * tid]     = e0;
        g_off[2 * tid + 1] = e0 + a;
        s_cur[2 * tid]     = e0;
        s_cur[2 * tid + 1] = e0 + a;
        if (tid == THREADS - 1) g_off[NSPEC] = incl;
        __syncthreads();

        // scatter both reaction types into the unified sorted entry array
        for (int r = tid; r < NR1; r += THREADS) {
            const int p   = i1p[r];
            const int pos = atomicAdd(&s_cur[p], 1);
            g_e[pos] = make_int4(i1r[r], ONES_ROW, __float_as_int(k1[r]), p);
        }
        for (int r = tid; r < NR2; r += THREADS) {
            const int p   = i2p[r];
            const int pos = atomicAdd(&s_cur[p], 1);
            g_e[pos] = make_int4(i2r[2 * r], i2r[2 * r + 1], __float_as_int(k2[r]), p);
        }
        __threadfence();
        __syncthreads();
        if (tid == 0) atomicExch(&g_ready, 1);
        __syncthreads();   // otile scratch reuse below is now safe
    }

    // ================= all CTAs: load y tile (transposed) ==================
    if (tid < NB) t_s[tid] = t_in[b0 + tid];
    if (tid < NB) y_s[ONES_ROW * YP + tid] = 1.0f;

    const float4* y4 = (const float4*)(y_in + (size_t)b0 * NSPEC);
    for (int i = tid; i < NB * NSPEC / 4; i += THREADS) {
        const float4 v = y4[i];
        const int b = i >> 8;                 // 256 float4 per row
        const int s = (i & 255) * 4;
        y_s[(s + 0) * YP + b] = v.x;
        y_s[(s + 1) * YP + b] = v.y;
        y_s[(s + 2) * YP + b] = v.z;
        y_s[(s + 3) * YP + b] = v.w;
    }

    // wait for CSR (non-zero CTAs); CTA0 already has it
    if (blockIdx.x != 0) {
        if (tid == 0) {
            while (*(volatile int*)&g_ready == 0) __nanosleep(256);
            __threadfence();
        }
    }
    __syncthreads();

    // ================= hot loop =============================================
    float* otile = otile0 + warp * (32 * YP);
    int4*  sbuf  = sbuf_all + warp * 32;

    for (int pc = warp * PROD_PER_WARP; pc < (warp + 1) * PROD_PER_WARP; pc += 32) {
        const int j0 = g_off[pc];
        const int j1 = g_off[pc + 32];

        float    acc   = 0.0f;
        int      curp  = -1;
        unsigned wmask = 0u;

        // prefetch first entry block
        int4 epf;
        if (j0 + lane < j1) epf = g_e[j0 + lane];

        for (int base = j0; base < j1; base += 32) {
            const int n = min(32, j1 - base);
            __syncwarp();
            if (lane < n) sbuf[lane] = epf;
            __syncwarp();
            // prefetch next block (overlaps with inner loop)
            const int nb_ = base + 32;
            if (nb_ + lane < j1) epf = g_e[nb_ + lane];

#pragma unroll 4
            for (int t = 0; t < n; ++t) {
                const int4 ee = sbuf[t];
                const float y0 = y_s[ee.x * YP + lane];
                const float y1 = y_s[ee.y * YP + lane];
                if (ee.w != curp) {
                    if (curp >= 0) {
                        otile[(curp - pc) * YP + lane] = acc;
                        wmask |= 1u << (curp - pc);
                    }
                    acc  = 0.0f;
                    curp = ee.w;
                }
                acc = fmaf(__int_as_float(ee.z), y0 * y1, acc);
            }
        }
        if (curp >= 0) {
            otile[(curp - pc) * YP + lane] = acc;
            wmask |= 1u << (curp - pc);
        }
        __syncwarp();

        // transposed, coalesced store; unwritten products -> 0
        const float myv = ((wmask >> lane) & 1u) ? 1.0f : 0.0f;
#pragma unroll
        for (int row = 0; row < 32; ++row) {
            const float v = otile[lane * YP + row] * myv;
            y_out[(size_t)(b0 + row) * NSPEC + pc + lane] = v * t_s[row];
        }
        __syncwarp();
    }

    // ================= reset flags for next graph replay ===================
    __syncthreads();
    if (tid == 0) {
        const int d = atomicAdd(&g_done, 1);
        if (d == grid_size - 1) {
            atomicExch(&g_done, 0);
            atomicExch(&g_ready, 0);
        }
    }
}

// ---------------- launch ----------------------------------------------------
extern "C" void kernel_launch(void* const* d_in, const int* in_sizes, int n_in,
                              void* d_out, int out_size) {
    const float* t_in = (const float*)d_in[0];
    const float* y_in = (const float*)d_in[1];
    const float* k1   = (const float*)d_in[2];
    const float* k2   = (const float*)d_in[3];
    const int*   i1r  = (const int*)d_in[4];
    const int*   i1p  = (const int*)d_in[5];
    const int*   i2r  = (const int*)d_in[6];
    const int*   i2p  = (const int*)d_in[7];
    float* y_out = (float*)d_out;

    const int B    = in_sizes[0];
    const int grid = B / NB;           // 128 CTAs <= 148 SMs: all co-resident

    static int attr_set = 0;
    if (!attr_set) {
        cudaFuncSetAttribute(reaction_fused_kernel,
                             cudaFuncAttributeMaxDynamicSharedMemorySize, SMEM_BYTES);
        attr_set = 1;
    }
    reaction_fused_kernel<<<grid, THREADS, SMEM_BYTES>>>(
        t_in, y_in, k1, k2, i1r, i1p, i2r, i2p, y_out, grid);
}

// round 3
// speedup vs baseline: 1.5416x; 1.1244x over previous
#include <cuda_runtime.h>
#include <cstdint>

#define NSPEC 1024
#define NR1   2048
#define NR2   8192
#define NRTOT (NR1 + NR2)
#define NB    32                   // batches per CTA (lane = batch)
#define WARPS 20
#define THREADS (WARPS * 32)
#define NCHUNK 32                  // 32 product-chunks of 32 products
#define YP    33                   // padded row stride (floats)
#define ONES_ROW NSPEC
#define NSETUP 16                  // CTAs participating in scatter

// ---------------- device scratch ----------------
__device__ int  g_off[NSPEC + 1];
__device__ int  g_cur[NSPEC];      // monotonic across replays (mod-cnt trick)
__device__ int4 g_e[NRTOT];        // .x/.y = byte offs into y_s row space, .z = k bits,
                                   // .w = dst byte off (|1 on last entry of product)
__device__ int  g_flag1;           // off[] ready
__device__ int  g_ready;           // scatter done counter (target NSETUP)
__device__ int  g_done;            // CTA completion counter

// ---------------- smem layout (bytes) ----------------
#define SBUF_B   (WARPS * 32 * 16)                 // 10240
#define YS_B     ((NSPEC + 1) * YP * 4)            // 135300
#define TS_B     (NB * 4)                          // 128
#define OTILE_B  (WARPS * 32 * YP * 4)             // 84480
#define SMEM_BYTES (SBUF_B + YS_B + TS_B + OTILE_B)  // 230148

extern "C" __global__ void __launch_bounds__(THREADS, 1)
reaction_fused_kernel(const float* __restrict__ t_in,
                      const float* __restrict__ y_in,
                      const float* __restrict__ k1,
                      const float* __restrict__ k2,
                      const int*   __restrict__ i1r,
                      const int*   __restrict__ i1p,
                      const int*   __restrict__ i2r,
                      const int*   __restrict__ i2p,
                      float* __restrict__ y_out,
                      int grid_size) {
    extern __shared__ char smem[];
    int4*  sbuf_all = (int4*)smem;
    float* y_s      = (float*)(smem + SBUF_B);
    float* t_s      = (float*)(smem + SBUF_B + YS_B);
    char*  otile0   = smem + SBUF_B + YS_B + TS_B;

    const int tid  = threadIdx.x;
    const int lane = tid & 31;
    const int warp = tid >> 5;
    const int cta  = blockIdx.x;
    const int b0   = cta * NB;

    __shared__ int s_chunk;
    if (tid == 0) s_chunk = 0;

    // ============ setup: CTA0 hist+scan; CTAs 0..15 scatter 1/16 each ======
    if (cta == 0) {
        int* s_cnt  = (int*)otile0;            // 1024 ints (scratch, pre-hotloop)
        int* s_wsum = s_cnt + NSPEC;           // 16
        for (int i = tid; i < NSPEC; i += THREADS) s_cnt[i] = 0;
        __syncthreads();
        for (int i = tid; i < NR1; i += THREADS) atomicAdd(&s_cnt[i1p[i]], 1);
        for (int i = tid; i < NR2; i += THREADS) atomicAdd(&s_cnt[i2p[i]], 1);
        __syncthreads();
        if (tid < 512) {                       // 16 warps scan 2 bins/thread
            const int a = s_cnt[2 * tid];
            const int b = s_cnt[2 * tid + 1];
            int incl = a + b;
#pragma unroll
            for (int d = 1; d < 32; d <<= 1) {
                int n = __shfl_up_sync(0xFFFFFFFFu, incl, d);
                if (lane >= d) incl += n;
            }
            if (lane == 31) s_wsum[warp] = incl;
            __syncthreads();
            if (warp == 0) {
                int w = (lane < 16) ? s_wsum[lane] : 0;
#pragma unroll
                for (int d = 1; d < 32; d <<= 1) {
                    int n = __shfl_up_sync(0xFFFFFFFFu, w, d);
                    if (lane >= d) w += n;
                }
                if (lane < 16) s_wsum[lane] = w;
            }
            __syncthreads();
            if (warp > 0) incl += s_wsum[warp - 1];
            const int e0 = incl - a - b;
            g_off[2 * tid]     = e0;
            g_off[2 * tid + 1] = e0 + a;
            if (tid == 511) g_off[NSPEC] = incl;
        } else {
            __syncthreads(); __syncthreads();
        }
        __threadfence();
        __syncthreads();
        if (tid == 0) atomicExch(&g_flag1, 1);
    }

    if (cta < NSETUP) {
        if (cta != 0) {
            if (tid == 0) {
                while (atomicAdd(&g_flag1, 0) == 0) __nanosleep(128);
            }
            __syncthreads();
        }
        // scatter this CTA's 1/16 slice of both reaction types
        const int per1 = NR1 / NSETUP, per2 = NR2 / NSETUP;
        for (int r = cta * per1 + tid; r < (cta + 1) * per1; r += THREADS) {
            const int p    = i1p[r];
            const int o0   = g_off[p], o1 = g_off[p + 1];
            const int cnt  = o1 - o0;
            const int posP = atomicAdd(&g_cur[p], 1) % cnt;   // epoch-free
            const int last = (posP == cnt - 1) ? 1 : 0;
            g_e[o0 + posP] = make_int4(i1r[r] * (YP * 4), ONES_ROW * (YP * 4),
                                       __float_as_int(k1[r]),
                                       ((p & 31) * (YP * 4)) | last);
        }
        for (int r = cta * per2 + tid; r < (cta + 1) * per2; r += THREADS) {
            const int p    = i2p[r];
            const int o0   = g_off[p], o1 = g_off[p + 1];
            const int cnt  = o1 - o0;
            const int posP = atomicAdd(&g_cur[p], 1) % cnt;
            const int last = (posP == cnt - 1) ? 1 : 0;
            g_e[o0 + posP] = make_int4(i2r[2 * r] * (YP * 4), i2r[2 * r + 1] * (YP * 4),
                                       __float_as_int(k2[r]),
                                       ((p & 31) * (YP * 4)) | last);
        }
        __threadfence();
        __syncthreads();
        if (tid == 0) atomicAdd(&g_ready, 1);
    }

    // ============ all CTAs: load y tile transposed into smem ================
    if (tid < NB) t_s[tid] = t_in[b0 + tid];
    if (tid < NB) y_s[ONES_ROW * YP + tid] = 1.0f;
    {
        const float4* y4 = (const float4*)(y_in + (size_t)b0 * NSPEC);
        for (int i = tid; i < NB * NSPEC / 4; i += THREADS) {
            const float4 v = y4[i];
            const int b = i >> 8;
            const int s = (i & 255) * 4;
            y_s[(s + 0) * YP + b] = v.x;
            y_s[(s + 1) * YP + b] = v.y;
            y_s[(s + 2) * YP + b] = v.z;
            y_s[(s + 3) * YP + b] = v.w;
        }
    }

    // wait for CSR ready
    if (tid == 0) {
        while (atomicAdd(&g_ready, 0) < NSETUP) __nanosleep(128);
    }
    __syncthreads();   // also fences: otile scratch (CTA0) safe to reuse now

    // ============ hot loop: work-stealing over 32 product chunks ============
    const char* ysl   = (const char*)y_s + lane * 4;     // lane-baked base
    char*       otl   = otile0 + (warp * 32 * YP + lane) * 4;
    int4*       sbuf  = sbuf_all + warp * 32;

    for (;;) {
        int c;
        if (lane == 0) c = atomicAdd(&s_chunk, 1);
        c = __shfl_sync(0xFFFFFFFFu, c, 0);
        if (c >= NCHUNK) break;
        const int pc = c * 32;
        const int j0 = g_off[pc];
        const int j1 = g_off[pc + 32];

        // pre-zero this warp's otile chunk
#pragma unroll
        for (int pp = 0; pp < 32; ++pp)
            *(float*)(otl + pp * (YP * 4)) = 0.0f;

        float acc = 0.0f;
        int4 epf;
        if (j0 + lane < j1) epf = g_e[j0 + lane];

        for (int base = j0; base < j1; base += 32) {
            const int n = min(32, j1 - base);
            __syncwarp();
            if (lane < n) sbuf[lane] = epf;
            __syncwarp();
            const int nxt = base + 32;
            if (nxt + lane < j1) epf = g_e[nxt + lane];

#pragma unroll 8
            for (int t = 0; t < n; ++t) {
                const int4 ee = sbuf[t];
                const float y0 = *(const float*)(ysl + ee.x);
                const float y1 = *(const float*)(ysl + ee.y);
                acc = fmaf(__int_as_float(ee.z), y0 * y1, acc);
                if (ee.w & 1) {                       // last entry of product
                    *(float*)(otl + (ee.w & ~3)) = acc;
                    acc = 0.0f;
                }
            }
        }
        __syncwarp();

        // transposed coalesced store (row = batch), fold t_in here
        const float* ot_rd = (const float*)(otile0 + (warp * 32 * YP + lane * YP) * 4);
#pragma unroll
        for (int row = 0; row < 32; ++row) {
            y_out[(size_t)(b0 + row) * NSPEC + pc + lane] = ot_rd[row] * t_s[row];
        }
        __syncwarp();
    }

    // ============ reset flags for next replay ===============================
    __syncthreads();
    if (tid == 0) {
        const int d = atomicAdd(&g_done, 1);
        if (d == grid_size - 1) {
            atomicExch(&g_ready, 0);
            atomicExch(&g_flag1, 0);
            atomicExch(&g_done, 0);
            // g_cur intentionally NOT reset (mod-cnt epoch trick)
        }
    }
}

// ---------------- launch -----------------------------------------------------
extern "C" void kernel_launch(void* const* d_in, const int* in_sizes, int n_in,
                              void* d_out, int out_size) {
    const float* t_in = (const float*)d_in[0];
    const float* y_in = (const float*)d_in[1];
    const float* k1   = (const float*)d_in[2];
    const float* k2   = (const float*)d_in[3];
    const int*   i1r  = (const int*)d_in[4];
    const int*   i1p  = (const int*)d_in[5];
    const int*   i2r  = (const int*)d_in[6];
    const int*   i2p  = (const int*)d_in[7];
    float* y_out = (float*)d_out;

    const int B    = in_sizes[0];
    const int grid = B / NB;   // 128

    cudaFuncSetAttribute(reaction_fused_kernel,
                         cudaFuncAttributeMaxDynamicSharedMemorySize, SMEM_BYTES);
    reaction_fused_kernel<<<grid, THREADS, SMEM_BYTES>>>(
        t_in, y_in, k1, k2, i1r, i1p, i2r, i2p, y_out, grid);
}